// round 3
// baseline (speedup 1.0000x reference)
#include <cuda_runtime.h>
#include <cuda_fp16.h>
#include <math.h>

#define MAXN 100000

// Scratch (allocation-free rule: device globals)
__device__ __half g_Mh[(size_t)MAXN * 64];  // fp16 relu(x @ W_msg + b_msg)
__device__ float  g_agg[(size_t)MAXN * 64]; // scatter-add destination (f32)
__device__ float  g_deg[MAXN];              // in-degree

// ---------------------------------------------------------------------------
// Prep: g_Mh = fp16(relu(X @ W_msg + b_msg)).
// 128 threads/block, 128-row tile, 8x8 register tile per thread.
// ---------------------------------------------------------------------------
__global__ __launch_bounds__(128) void k_prep_m(const float* __restrict__ X,
                                                const float* __restrict__ W,
                                                const float* __restrict__ b,
                                                int N)
{
    __shared__ float xs[64 * 128];   // xs[k*128 + row]
    __shared__ float ws[64 * 64];    // ws[k*64 + col]

    int tid = threadIdx.x;
    int tx = tid & 7;                // col group (8 cols)
    int ty = tid >> 3;               // row group (8 rows)
    int rowBase = blockIdx.x << 7;

    // load W: 4096 floats = 1024 float4, 8 per thread
    {
        const float4* Wv = (const float4*)W;
        float4* wsv = (float4*)ws;
        #pragma unroll
        for (int i = 0; i < 8; i++) wsv[tid + 128 * i] = Wv[tid + 128 * i];
    }
    // stage x rows transposed: thread tid stages row rowBase+tid
    {
        int grow = rowBase + tid;
        const float4* xrow = (const float4*)(X + (size_t)grow * 64);
        #pragma unroll
        for (int f = 0; f < 16; f++) {
            float4 v = make_float4(0.f, 0.f, 0.f, 0.f);
            if (grow < N) v = xrow[f];
            xs[(4 * f + 0) * 128 + tid] = v.x;
            xs[(4 * f + 1) * 128 + tid] = v.y;
            xs[(4 * f + 2) * 128 + tid] = v.z;
            xs[(4 * f + 3) * 128 + tid] = v.w;
        }
    }
    __syncthreads();

    int r0 = ty * 8, c0 = tx * 8;
    float acc[8][8];
    #pragma unroll
    for (int i = 0; i < 8; i++)
        #pragma unroll
        for (int j = 0; j < 8; j++) acc[i][j] = 0.f;

    #pragma unroll 8
    for (int k = 0; k < 64; k++) {
        float a[8], bb[8];
        *(float4*)&a[0]  = *(float4*)&xs[k * 128 + r0];
        *(float4*)&a[4]  = *(float4*)&xs[k * 128 + r0 + 4];
        *(float4*)&bb[0] = *(float4*)&ws[k * 64 + c0];
        *(float4*)&bb[4] = *(float4*)&ws[k * 64 + c0 + 4];
        #pragma unroll
        for (int i = 0; i < 8; i++)
            #pragma unroll
            for (int j = 0; j < 8; j++)
                acc[i][j] += a[i] * bb[j];
    }

    float bias[8];
    *(float4*)&bias[0] = *(const float4*)&b[c0];
    *(float4*)&bias[4] = *(const float4*)&b[c0 + 4];

    #pragma unroll
    for (int i = 0; i < 8; i++) {
        int grow = rowBase + r0 + i;
        if (grow < N) {
            __half2 h0 = __floats2half2_rn(fmaxf(acc[i][0] + bias[0], 0.f),
                                           fmaxf(acc[i][1] + bias[1], 0.f));
            __half2 h1 = __floats2half2_rn(fmaxf(acc[i][2] + bias[2], 0.f),
                                           fmaxf(acc[i][3] + bias[3], 0.f));
            __half2 h2 = __floats2half2_rn(fmaxf(acc[i][4] + bias[4], 0.f),
                                           fmaxf(acc[i][5] + bias[5], 0.f));
            __half2 h3 = __floats2half2_rn(fmaxf(acc[i][6] + bias[6], 0.f),
                                           fmaxf(acc[i][7] + bias[7], 0.f));
            uint4 p;
            p.x = *(unsigned*)&h0; p.y = *(unsigned*)&h1;
            p.z = *(unsigned*)&h2; p.w = *(unsigned*)&h3;
            *(uint4*)(g_Mh + (size_t)grow * 64 + c0) = p;
        }
    }
}

// ---------------------------------------------------------------------------
// Edge scatter: 8 lanes per edge, 4 edges per thread (4 gathers in flight).
// ---------------------------------------------------------------------------
__device__ __forceinline__ void unpack_scale(uint4 r, float w, float out[8])
{
    __half2 h; float2 f;
    h = *(__half2*)&r.x; f = __half22float2(h); out[0] = f.x * w; out[1] = f.y * w;
    h = *(__half2*)&r.y; f = __half22float2(h); out[2] = f.x * w; out[3] = f.y * w;
    h = *(__half2*)&r.z; f = __half22float2(h); out[4] = f.x * w; out[5] = f.y * w;
    h = *(__half2*)&r.w; f = __half22float2(h); out[6] = f.x * w; out[7] = f.y * w;
}

__global__ void k_scatter(const int* __restrict__ ei,
                          const float* __restrict__ ew, int E, int Eq)
{
    int gid = blockIdx.x * blockDim.x + threadIdx.x;
    int t = gid >> 3;
    if (t >= Eq) return;
    int g = gid & 7;

    int  e[4];
    bool has[4];
    int  src[4], dst[4];
    float w[4];
    #pragma unroll
    for (int j = 0; j < 4; j++) {
        e[j] = t + j * Eq;
        has[j] = (e[j] < E);
        int ee = has[j] ? e[j] : 0;
        src[j] = __ldg(ei + ee);
        dst[j] = __ldg(ei + E + ee);
        w[j]   = has[j] ? __ldg(ew + ee) : 0.f;
    }

    // 4 independent 16B gathers in flight
    uint4 r[4];
    #pragma unroll
    for (int j = 0; j < 4; j++)
        r[j] = *(const uint4*)(g_Mh + (size_t)src[j] * 64 + g * 8);

    #pragma unroll
    for (int j = 0; j < 4; j++) {
        if (!has[j]) continue;
        float m[8];
        unpack_scale(r[j], w[j], m);
        float* p = g_agg + (size_t)dst[j] * 64 + g * 8;
        asm volatile("red.global.add.v4.f32 [%0], {%1, %2, %3, %4};"
                     :: "l"(p), "f"(m[0]), "f"(m[1]), "f"(m[2]), "f"(m[3]) : "memory");
        asm volatile("red.global.add.v4.f32 [%0], {%1, %2, %3, %4};"
                     :: "l"(p + 4), "f"(m[4]), "f"(m[5]), "f"(m[6]), "f"(m[7]) : "memory");
    }

    if (g == 0) {
        #pragma unroll
        for (int j = 0; j < 4; j++) {
            if (has[j]) {
                float* dp = g_deg + dst[j];
                asm volatile("red.global.add.f32 [%0], %1;"
                             :: "l"(dp), "f"(1.0f) : "memory");
            }
        }
    }
}

// ---------------------------------------------------------------------------
// Combine (fused K=128): h = relu([x || agg/deg] @ W_upd + b_upd), L2-normalize.
// 128 threads/block, 128-row tile, 8x8 register tile, shfl-based row norms.
// ---------------------------------------------------------------------------
__global__ __launch_bounds__(128) void k_combine(const float* __restrict__ X,
                                                 const float* __restrict__ Wupd,
                                                 const float* __restrict__ b,
                                                 float* __restrict__ out, int N)
{
    __shared__ float xs[64 * 128];   // staged tile (x, then agg/deg)
    __shared__ float ws[128 * 64];   // full W_upd

    int tid = threadIdx.x;
    int tx = tid & 7;
    int ty = tid >> 3;
    int rowBase = blockIdx.x << 7;

    // load full W_upd: 8192 floats = 2048 float4, 16 per thread
    {
        const float4* Wv = (const float4*)Wupd;
        float4* wsv = (float4*)ws;
        #pragma unroll
        for (int i = 0; i < 16; i++) wsv[tid + 128 * i] = Wv[tid + 128 * i];
    }
    // stage x rows transposed
    {
        int grow = rowBase + tid;
        const float4* xrow = (const float4*)(X + (size_t)grow * 64);
        #pragma unroll
        for (int f = 0; f < 16; f++) {
            float4 v = make_float4(0.f, 0.f, 0.f, 0.f);
            if (grow < N) v = xrow[f];
            xs[(4 * f + 0) * 128 + tid] = v.x;
            xs[(4 * f + 1) * 128 + tid] = v.y;
            xs[(4 * f + 2) * 128 + tid] = v.z;
            xs[(4 * f + 3) * 128 + tid] = v.w;
        }
    }
    __syncthreads();

    int r0 = ty * 8, c0 = tx * 8;
    float acc[8][8];
    #pragma unroll
    for (int i = 0; i < 8; i++)
        #pragma unroll
        for (int j = 0; j < 8; j++) acc[i][j] = 0.f;

    // K half 1: x @ W_upd[0:64]
    #pragma unroll 8
    for (int k = 0; k < 64; k++) {
        float a[8], bb[8];
        *(float4*)&a[0]  = *(float4*)&xs[k * 128 + r0];
        *(float4*)&a[4]  = *(float4*)&xs[k * 128 + r0 + 4];
        *(float4*)&bb[0] = *(float4*)&ws[k * 64 + c0];
        *(float4*)&bb[4] = *(float4*)&ws[k * 64 + c0 + 4];
        #pragma unroll
        for (int i = 0; i < 8; i++)
            #pragma unroll
            for (int j = 0; j < 8; j++)
                acc[i][j] += a[i] * bb[j];
    }
    __syncthreads();

    // restage with agg/deg
    {
        int grow = rowBase + tid;
        float s = 0.f;
        if (grow < N) s = 1.0f / fmaxf(g_deg[grow], 1.0f);
        const float4* arow = (const float4*)(g_agg + (size_t)grow * 64);
        #pragma unroll
        for (int f = 0; f < 16; f++) {
            float4 v = make_float4(0.f, 0.f, 0.f, 0.f);
            if (grow < N) v = arow[f];
            xs[(4 * f + 0) * 128 + tid] = v.x * s;
            xs[(4 * f + 1) * 128 + tid] = v.y * s;
            xs[(4 * f + 2) * 128 + tid] = v.z * s;
            xs[(4 * f + 3) * 128 + tid] = v.w * s;
        }
    }
    __syncthreads();

    // K half 2: agg @ W_upd[64:128]
    #pragma unroll 8
    for (int k = 0; k < 64; k++) {
        float a[8], bb[8];
        *(float4*)&a[0]  = *(float4*)&xs[k * 128 + r0];
        *(float4*)&a[4]  = *(float4*)&xs[k * 128 + r0 + 4];
        *(float4*)&bb[0] = *(float4*)&ws[(64 + k) * 64 + c0];
        *(float4*)&bb[4] = *(float4*)&ws[(64 + k) * 64 + c0 + 4];
        #pragma unroll
        for (int i = 0; i < 8; i++)
            #pragma unroll
            for (int j = 0; j < 8; j++)
                acc[i][j] += a[i] * bb[j];
    }

    // epilogue: +bias, relu, row sum-of-squares, shfl-reduce over 8 col-group lanes
    float bias[8];
    *(float4*)&bias[0] = *(const float4*)&b[c0];
    *(float4*)&bias[4] = *(const float4*)&b[c0 + 4];

    float rsum[8];
    #pragma unroll
    for (int i = 0; i < 8; i++) {
        float s = 0.f;
        #pragma unroll
        for (int j = 0; j < 8; j++) {
            float h = fmaxf(acc[i][j] + bias[j], 0.f);
            acc[i][j] = h;
            s += h * h;
        }
        rsum[i] = s;
    }
    #pragma unroll
    for (int m = 1; m < 8; m <<= 1) {
        #pragma unroll
        for (int i = 0; i < 8; i++)
            rsum[i] += __shfl_xor_sync(0xffffffffu, rsum[i], m, 8);
    }

    #pragma unroll
    for (int i = 0; i < 8; i++) {
        int grow = rowBase + r0 + i;
        if (grow < N) {
            float sc = 1.0f / fmaxf(sqrtf(rsum[i]), 1e-12f);
            float4 v0, v1;
            v0.x = acc[i][0] * sc; v0.y = acc[i][1] * sc;
            v0.z = acc[i][2] * sc; v0.w = acc[i][3] * sc;
            v1.x = acc[i][4] * sc; v1.y = acc[i][5] * sc;
            v1.z = acc[i][6] * sc; v1.w = acc[i][7] * sc;
            float* op = out + (size_t)grow * 64 + c0;
            *(float4*)op = v0;
            *(float4*)(op + 4) = v1;
        }
    }
}

// ---------------------------------------------------------------------------
extern "C" void kernel_launch(void* const* d_in, const int* in_sizes, int n_in,
                              void* d_out, int out_size)
{
    const float* x    = (const float*)d_in[0];
    const int*   ei   = (const int*)  d_in[1];
    const float* ew   = (const float*)d_in[2];
    const float* Wmsg = (const float*)d_in[3];
    const float* bmsg = (const float*)d_in[4];
    const float* Wupd = (const float*)d_in[5];
    const float* bupd = (const float*)d_in[6];
    float* out = (float*)d_out;

    int N = in_sizes[0] / 64;
    int E = in_sizes[2];

    // zero scratch via graph-capturable memset nodes
    void* aggp = nullptr; cudaGetSymbolAddress(&aggp, g_agg);
    void* degp = nullptr; cudaGetSymbolAddress(&degp, g_deg);
    cudaMemsetAsync(aggp, 0, (size_t)N * 64 * sizeof(float));
    cudaMemsetAsync(degp, 0, (size_t)N * sizeof(float));

    int gb = (N + 127) / 128;
    k_prep_m<<<gb, 128>>>(x, Wmsg, bmsg, N);

    int Eq = (E + 3) / 4;
    long long sth = (long long)Eq * 8;
    int sblocks = (int)((sth + 255) / 256);
    k_scatter<<<sblocks, 256>>>(ei, ew, E, Eq);

    k_combine<<<gb, 128>>>(x, Wupd, bupd, out, N);
}

// round 4
// speedup vs baseline: 1.3689x; 1.3689x over previous
#include <cuda_runtime.h>
#include <cuda_fp16.h>
#include <math.h>

#define MAXN 100000
#define XS 72   // smem row stride in halves (144B -> conflict-free ldmatrix)

__device__ __half g_Mh[(size_t)MAXN * 64];
__device__ float  g_agg[(size_t)MAXN * 64];
__device__ float  g_deg[MAXN];

__device__ __forceinline__ unsigned smem_u32(const void* p) {
    return (unsigned)__cvta_generic_to_shared(p);
}
__device__ __forceinline__ void ldsm_x4(unsigned& r0, unsigned& r1, unsigned& r2, unsigned& r3, unsigned a) {
    asm volatile("ldmatrix.sync.aligned.m8n8.x4.shared.b16 {%0,%1,%2,%3}, [%4];"
                 : "=r"(r0), "=r"(r1), "=r"(r2), "=r"(r3) : "r"(a));
}
__device__ __forceinline__ void ldsm_x2t(unsigned& r0, unsigned& r1, unsigned a) {
    asm volatile("ldmatrix.sync.aligned.m8n8.x2.trans.shared.b16 {%0,%1}, [%2];"
                 : "=r"(r0), "=r"(r1) : "r"(a));
}
__device__ __forceinline__ void mma16816(float c[4], const unsigned a[4], unsigned b0, unsigned b1) {
    asm volatile("mma.sync.aligned.m16n8k16.row.col.f32.f16.f16.f32 "
                 "{%0,%1,%2,%3}, {%4,%5,%6,%7}, {%8,%9}, {%0,%1,%2,%3};"
                 : "+f"(c[0]), "+f"(c[1]), "+f"(c[2]), "+f"(c[3])
                 : "r"(a[0]), "r"(a[1]), "r"(a[2]), "r"(a[3]), "r"(b0), "r"(b1));
}

// ---------------------------------------------------------------------------
// Prep: g_Mh = fp16(relu(X @ W_msg + b_msg)).  256 thr, 128-row tile, HMMA.
// ---------------------------------------------------------------------------
__global__ __launch_bounds__(256) void k_prep(const float* __restrict__ X,
                                              const float* __restrict__ W,
                                              const float* __restrict__ b,
                                              int N)
{
    __shared__ __half xs[128 * XS];
    __shared__ __half ws[64 * XS];

    int tid = threadIdx.x, lane = tid & 31, w = tid >> 5;
    int rowBase = blockIdx.x << 7;

    // stage W (64x64 f32 -> fp16): 1024 float4
    #pragma unroll
    for (int i = 0; i < 4; i++) {
        int idx = tid + i * 256;
        int r = idx >> 4, f = idx & 15;
        float4 v = ((const float4*)W)[idx];
        __half2 h0 = __floats2half2_rn(v.x, v.y);
        __half2 h1 = __floats2half2_rn(v.z, v.w);
        uint2 p; p.x = *(unsigned*)&h0; p.y = *(unsigned*)&h1;
        *(uint2*)&ws[r * XS + f * 4] = p;
    }
    // stage x tile (128x64 f32 -> fp16): 2048 float4
    #pragma unroll
    for (int i = 0; i < 8; i++) {
        int idx = tid + i * 256;
        int r = idx >> 4, f = idx & 15;
        int grow = rowBase + r;
        float4 v = make_float4(0.f, 0.f, 0.f, 0.f);
        if (grow < N) v = ((const float4*)(X + (size_t)grow * 64))[f];
        __half2 h0 = __floats2half2_rn(v.x, v.y);
        __half2 h1 = __floats2half2_rn(v.z, v.w);
        uint2 p; p.x = *(unsigned*)&h0; p.y = *(unsigned*)&h1;
        *(uint2*)&xs[r * XS + f * 4] = p;
    }
    __syncthreads();

    int mrow = w * 16;
    unsigned A[4][4];
    #pragma unroll
    for (int kt = 0; kt < 4; kt++) {
        unsigned addr = smem_u32(&xs[(mrow + (lane & 15)) * XS + kt * 16 + ((lane >> 4) << 3)]);
        ldsm_x4(A[kt][0], A[kt][1], A[kt][2], A[kt][3], addr);
    }

    int r0 = rowBase + mrow + (lane >> 2);
    int r1 = r0 + 8;
    #pragma unroll
    for (int n = 0; n < 8; n++) {
        float c[4] = {0.f, 0.f, 0.f, 0.f};
        #pragma unroll
        for (int kt = 0; kt < 4; kt++) {
            unsigned b0, b1;
            unsigned addr = smem_u32(&ws[(kt * 16 + (lane & 15)) * XS + n * 8]);
            ldsm_x2t(b0, b1, addr);
            mma16816(c, A[kt], b0, b1);
        }
        int col = n * 8 + ((lane & 3) << 1);
        float bv0 = __ldg(b + col), bv1 = __ldg(b + col + 1);
        if (r0 < N) {
            __half2 h = __floats2half2_rn(fmaxf(c[0] + bv0, 0.f), fmaxf(c[1] + bv1, 0.f));
            *(__half2*)(g_Mh + (size_t)r0 * 64 + col) = h;
        }
        if (r1 < N) {
            __half2 h = __floats2half2_rn(fmaxf(c[2] + bv0, 0.f), fmaxf(c[3] + bv1, 0.f));
            *(__half2*)(g_Mh + (size_t)r1 * 64 + col) = h;
        }
    }
}

// ---------------------------------------------------------------------------
// Edge scatter: 8 lanes per edge, 4 edges per thread (4 gathers in flight).
// ---------------------------------------------------------------------------
__device__ __forceinline__ void unpack_scale(uint4 r, float w, float out[8])
{
    __half2 h; float2 f;
    h = *(__half2*)&r.x; f = __half22float2(h); out[0] = f.x * w; out[1] = f.y * w;
    h = *(__half2*)&r.y; f = __half22float2(h); out[2] = f.x * w; out[3] = f.y * w;
    h = *(__half2*)&r.z; f = __half22float2(h); out[4] = f.x * w; out[5] = f.y * w;
    h = *(__half2*)&r.w; f = __half22float2(h); out[6] = f.x * w; out[7] = f.y * w;
}

__global__ void k_scatter(const int* __restrict__ ei,
                          const float* __restrict__ ew, int E, int Eq)
{
    int gid = blockIdx.x * blockDim.x + threadIdx.x;
    int t = gid >> 3;
    if (t >= Eq) return;
    int g = gid & 7;

    bool has[4];
    int  src[4], dst[4];
    float w[4];
    #pragma unroll
    for (int j = 0; j < 4; j++) {
        int e = t + j * Eq;
        has[j] = (e < E);
        int ee = has[j] ? e : 0;
        src[j] = __ldg(ei + ee);
        dst[j] = __ldg(ei + E + ee);
        w[j]   = has[j] ? __ldg(ew + ee) : 0.f;
    }

    uint4 r[4];
    #pragma unroll
    for (int j = 0; j < 4; j++)
        r[j] = *(const uint4*)(g_Mh + (size_t)src[j] * 64 + g * 8);

    #pragma unroll
    for (int j = 0; j < 4; j++) {
        if (!has[j]) continue;
        float m[8];
        unpack_scale(r[j], w[j], m);
        float* p = g_agg + (size_t)dst[j] * 64 + g * 8;
        asm volatile("red.global.add.v4.f32 [%0], {%1, %2, %3, %4};"
                     :: "l"(p), "f"(m[0]), "f"(m[1]), "f"(m[2]), "f"(m[3]) : "memory");
        asm volatile("red.global.add.v4.f32 [%0], {%1, %2, %3, %4};"
                     :: "l"(p + 4), "f"(m[4]), "f"(m[5]), "f"(m[6]), "f"(m[7]) : "memory");
    }

    if (g == 0) {
        #pragma unroll
        for (int j = 0; j < 4; j++) {
            if (has[j]) {
                float* dp = g_deg + dst[j];
                asm volatile("red.global.add.f32 [%0], %1;"
                             :: "l"(dp), "f"(1.0f) : "memory");
            }
        }
    }
}

// ---------------------------------------------------------------------------
// Combine (K=128 fused): h = relu([x || agg/deg] @ W_upd + b_upd), L2-normalize.
// 256 thr, 128-row tile, HMMA, accumulators persistent across both K halves.
// ---------------------------------------------------------------------------
__global__ __launch_bounds__(256) void k_combine(const float* __restrict__ X,
                                                 const float* __restrict__ Wupd,
                                                 const float* __restrict__ b,
                                                 float* __restrict__ out, int N)
{
    __shared__ __half xs[128 * XS];
    __shared__ __half ws[128 * XS];

    int tid = threadIdx.x, lane = tid & 31, w = tid >> 5;
    int rowBase = blockIdx.x << 7;

    // stage full W_upd (128x64): 2048 float4
    #pragma unroll
    for (int i = 0; i < 8; i++) {
        int idx = tid + i * 256;
        int r = idx >> 4, f = idx & 15;
        float4 v = ((const float4*)Wupd)[idx];
        __half2 h0 = __floats2half2_rn(v.x, v.y);
        __half2 h1 = __floats2half2_rn(v.z, v.w);
        uint2 p; p.x = *(unsigned*)&h0; p.y = *(unsigned*)&h1;
        *(uint2*)&ws[r * XS + f * 4] = p;
    }
    // stage x tile
    #pragma unroll
    for (int i = 0; i < 8; i++) {
        int idx = tid + i * 256;
        int r = idx >> 4, f = idx & 15;
        int grow = rowBase + r;
        float4 v = make_float4(0.f, 0.f, 0.f, 0.f);
        if (grow < N) v = ((const float4*)(X + (size_t)grow * 64))[f];
        __half2 h0 = __floats2half2_rn(v.x, v.y);
        __half2 h1 = __floats2half2_rn(v.z, v.w);
        uint2 p; p.x = *(unsigned*)&h0; p.y = *(unsigned*)&h1;
        *(uint2*)&xs[r * XS + f * 4] = p;
    }
    __syncthreads();

    int mrow = w * 16;
    float c[8][4];
    #pragma unroll
    for (int n = 0; n < 8; n++)
        #pragma unroll
        for (int q = 0; q < 4; q++) c[n][q] = 0.f;

    unsigned A[4][4];
    // pass 1: x @ W_upd[0:64]
    #pragma unroll
    for (int kt = 0; kt < 4; kt++) {
        unsigned addr = smem_u32(&xs[(mrow + (lane & 15)) * XS + kt * 16 + ((lane >> 4) << 3)]);
        ldsm_x4(A[kt][0], A[kt][1], A[kt][2], A[kt][3], addr);
    }
    #pragma unroll
    for (int n = 0; n < 8; n++) {
        #pragma unroll
        for (int kt = 0; kt < 4; kt++) {
            unsigned b0, b1;
            unsigned addr = smem_u32(&ws[(kt * 16 + (lane & 15)) * XS + n * 8]);
            ldsm_x2t(b0, b1, addr);
            mma16816(c[n], A[kt], b0, b1);
        }
    }
    __syncthreads();

    // restage with agg/deg
    #pragma unroll
    for (int i = 0; i < 8; i++) {
        int idx = tid + i * 256;
        int r = idx >> 4, f = idx & 15;
        int grow = rowBase + r;
        float4 v = make_float4(0.f, 0.f, 0.f, 0.f);
        float s = 0.f;
        if (grow < N) {
            s = 1.0f / fmaxf(g_deg[grow], 1.0f);
            v = ((const float4*)(g_agg + (size_t)grow * 64))[f];
        }
        __half2 h0 = __floats2half2_rn(v.x * s, v.y * s);
        __half2 h1 = __floats2half2_rn(v.z * s, v.w * s);
        uint2 p; p.x = *(unsigned*)&h0; p.y = *(unsigned*)&h1;
        *(uint2*)&xs[r * XS + f * 4] = p;
    }
    __syncthreads();

    // pass 2: agg @ W_upd[64:128]
    #pragma unroll
    for (int kt = 0; kt < 4; kt++) {
        unsigned addr = smem_u32(&xs[(mrow + (lane & 15)) * XS + kt * 16 + ((lane >> 4) << 3)]);
        ldsm_x4(A[kt][0], A[kt][1], A[kt][2], A[kt][3], addr);
    }
    #pragma unroll
    for (int n = 0; n < 8; n++) {
        #pragma unroll
        for (int kt = 0; kt < 4; kt++) {
            unsigned b0, b1;
            unsigned addr = smem_u32(&ws[((64 + kt * 16) + (lane & 15)) * XS + n * 8]);
            ldsm_x2t(b0, b1, addr);
            mma16816(c[n], A[kt], b0, b1);
        }
    }

    // epilogue: bias, relu, row norms via shfl over the 4 lanes of each row group
    float ss0 = 0.f, ss1 = 0.f;
    #pragma unroll
    for (int n = 0; n < 8; n++) {
        int col = n * 8 + ((lane & 3) << 1);
        float bv0 = __ldg(b + col), bv1 = __ldg(b + col + 1);
        float h0 = fmaxf(c[n][0] + bv0, 0.f);
        float h1 = fmaxf(c[n][1] + bv1, 0.f);
        float h2 = fmaxf(c[n][2] + bv0, 0.f);
        float h3 = fmaxf(c[n][3] + bv1, 0.f);
        c[n][0] = h0; c[n][1] = h1; c[n][2] = h2; c[n][3] = h3;
        ss0 += h0 * h0 + h1 * h1;
        ss1 += h2 * h2 + h3 * h3;
    }
    ss0 += __shfl_xor_sync(0xffffffffu, ss0, 1);
    ss0 += __shfl_xor_sync(0xffffffffu, ss0, 2);
    ss1 += __shfl_xor_sync(0xffffffffu, ss1, 1);
    ss1 += __shfl_xor_sync(0xffffffffu, ss1, 2);

    float sc0 = 1.0f / fmaxf(sqrtf(ss0), 1e-12f);
    float sc1 = 1.0f / fmaxf(sqrtf(ss1), 1e-12f);

    int r0 = rowBase + mrow + (lane >> 2);
    int r1 = r0 + 8;
    #pragma unroll
    for (int n = 0; n < 8; n++) {
        int col = n * 8 + ((lane & 3) << 1);
        if (r0 < N) {
            float2 v; v.x = c[n][0] * sc0; v.y = c[n][1] * sc0;
            *(float2*)(out + (size_t)r0 * 64 + col) = v;
        }
        if (r1 < N) {
            float2 v; v.x = c[n][2] * sc1; v.y = c[n][3] * sc1;
            *(float2*)(out + (size_t)r1 * 64 + col) = v;
        }
    }
}

// ---------------------------------------------------------------------------
extern "C" void kernel_launch(void* const* d_in, const int* in_sizes, int n_in,
                              void* d_out, int out_size)
{
    const float* x    = (const float*)d_in[0];
    const int*   ei   = (const int*)  d_in[1];
    const float* ew   = (const float*)d_in[2];
    const float* Wmsg = (const float*)d_in[3];
    const float* bmsg = (const float*)d_in[4];
    const float* Wupd = (const float*)d_in[5];
    const float* bupd = (const float*)d_in[6];
    float* out = (float*)d_out;

    int N = in_sizes[0] / 64;
    int E = in_sizes[2];

    void* aggp = nullptr; cudaGetSymbolAddress(&aggp, g_agg);
    void* degp = nullptr; cudaGetSymbolAddress(&degp, g_deg);
    cudaMemsetAsync(aggp, 0, (size_t)N * 64 * sizeof(float));
    cudaMemsetAsync(degp, 0, (size_t)N * sizeof(float));

    int gb = (N + 127) / 128;
    k_prep<<<gb, 256>>>(x, Wmsg, bmsg, N);

    int Eq = (E + 3) / 4;
    long long sth = (long long)Eq * 8;
    int sblocks = (int)((sth + 255) / 256);
    k_scatter<<<sblocks, 256>>>(ei, ew, E, Eq);

    k_combine<<<gb, 256>>>(x, Wupd, bupd, out, N);
}